// round 3
// baseline (speedup 1.0000x reference)
#include <cuda_runtime.h>
#include <cstdint>

#define IN_FEAT   128
#define CODE_DIM  32
#define NUM_CODES 256
#define OUT_FEAT  128

#define TPB 512            // threads per block
#define RPB 1024           // rows per block (64 rows per warp, 2 per lane)
#define SSTRIDE 1026       // smem row stride (floats)

#define TIE_TH 5e-4f       // score-gap threshold for fp64 refinement
#define TIE_CAP (1 << 20)

// Precomputed fused parameters (device globals: no allocation allowed)
__device__ float  g_WcT[IN_FEAT * CODE_DIM];     // [m][j]  (W_pin @ W_down) transposed
__device__ double g_Wc64[IN_FEAT * CODE_DIM];    // fp64 copy for refinement
__device__ float  g_bc [CODE_DIM];               // W_pin @ b_down + b_pin
__device__ double g_bc64[CODE_DIM];
__device__ float  g_cbT[CODE_DIM * NUM_CODES];   // [j][c]  codebook transposed
__device__ float  g_s0 [NUM_CODES];              // cb.bc - 0.5*||cb||^2
__device__ float  g_U  [NUM_CODES * OUT_FEAT];   // cb @ W_pout^T + b_pout
__device__ float  g_T  [NUM_CODES * OUT_FEAT];   // clip(U @ W_up^T + b_up)
__device__ int    g_cnt;                          // near-tie row counter
__device__ int    g_rows[TIE_CAP];                // near-tie row list

// ---- packed f32x2 helpers (sm_103a) ----
using u64 = unsigned long long;
__device__ __forceinline__ u64 pk2(float lo, float hi) {
    u64 r; asm("mov.b64 %0,{%1,%2};" : "=l"(r) : "f"(lo), "f"(hi)); return r;
}
__device__ __forceinline__ void upk2(u64 v, float& lo, float& hi) {
    asm("mov.b64 {%0,%1},%2;" : "=f"(lo), "=f"(hi) : "l"(v));
}
__device__ __forceinline__ u64 ffma2(u64 a, u64 b, u64 c) {
    u64 d; asm("fma.rn.f32x2 %0,%1,%2,%3;" : "=l"(d) : "l"(a), "l"(b), "l"(c)); return d;
}

// =================== precompute kernels (tiny, fp64 accumulation) ===================

__global__ void k_zero() { if (threadIdx.x == 0 && blockIdx.x == 0) g_cnt = 0; }

__global__ void k_pre_wc(const float* __restrict__ Wd, const float* __restrict__ bd,
                         const float* __restrict__ Wp, const float* __restrict__ bp) {
    int t = blockIdx.x * blockDim.x + threadIdx.x;
    if (t < IN_FEAT * CODE_DIM) {
        int m = t >> 5, j = t & 31;
        double s = 0.0;
        for (int k = 0; k < IN_FEAT; k++)
            s += (double)Wp[j * IN_FEAT + k] * (double)Wd[k * IN_FEAT + m];
        g_WcT[m * CODE_DIM + j]  = (float)s;
        g_Wc64[m * CODE_DIM + j] = s;
    }
    if (t < CODE_DIM) {
        double s = (double)bp[t];
        for (int k = 0; k < IN_FEAT; k++)
            s += (double)Wp[t * IN_FEAT + k] * (double)bd[k];
        g_bc[t]   = (float)s;
        g_bc64[t] = s;
    }
}

__global__ void k_pre_cb(const float* __restrict__ cb) {
    int t = blockIdx.x * blockDim.x + threadIdx.x;
    if (t < CODE_DIM * NUM_CODES) {
        int j = t >> 8, c = t & 255;
        g_cbT[j * NUM_CODES + c] = cb[c * CODE_DIM + j];
    }
    if (t < NUM_CODES) {
        double s = 0.0, n2 = 0.0;
        for (int j = 0; j < CODE_DIM; j++) {
            double v = (double)cb[t * CODE_DIM + j];
            s  += v * g_bc64[j];
            n2 += v * v;
        }
        g_s0[t] = (float)(s - 0.5 * n2);
    }
}

__global__ void k_pre_U(const float* __restrict__ cb, const float* __restrict__ Wpo,
                        const float* __restrict__ bpo) {
    int t = blockIdx.x * blockDim.x + threadIdx.x;   // 32768
    int c = t >> 7, o = t & 127;
    float s = bpo[o];
    for (int j = 0; j < CODE_DIM; j++)
        s = fmaf(cb[c * CODE_DIM + j], Wpo[o * CODE_DIM + j], s);
    g_U[c * OUT_FEAT + o] = s;
}

__global__ void k_pre_T(const float* __restrict__ Wu, const float* __restrict__ bu) {
    int t = blockIdx.x * blockDim.x + threadIdx.x;   // 32768
    int c = t >> 7, o = t & 127;
    float s = bu[o];
    for (int i = 0; i < OUT_FEAT; i++)
        s = fmaf(g_U[c * OUT_FEAT + i], Wu[o * OUT_FEAT + i], s);
    g_T[c * OUT_FEAT + o] = fminf(fmaxf(s, -1.0f), 1.0f);
}

// =================== main kernel ===================

__global__ __launch_bounds__(TPB, 1)
void k_main(const float* __restrict__ x, float* __restrict__ out,
            int nrows, long long out_size) {
    extern __shared__ float sm[];
    float* sWc  = sm;                       // 4096 floats  [m][j]
    float* sCb  = sWc + 4096;               // 8192 floats  [j][c]
    float* sS0  = sCb + 8192;               // 256 floats
    float* sBuf = sS0 + 256;                // 32*SSTRIDE floats (x-chunk / z, aliased)
    int*   sIdx = (int*)(sBuf + 32 * SSTRIDE);  // 1024 ints

    const int tid  = threadIdx.x;
    const int wid  = tid >> 5;
    const int lane = tid & 31;
    const int rowBase = blockIdx.x * RPB;

    for (int i = tid; i < 4096; i += TPB) sWc[i] = g_WcT[i];
    for (int i = tid; i < 8192; i += TPB) sCb[i] = g_cbT[i];
    if (tid < 256) sS0[tid] = g_s0[tid];

    const int rbase = wid * 64;
    const int r0 = rbase + 2 * lane;
    const int r1 = r0 + 1;

    // ---- phase A: z = x @ Wc^T ----
    u64 acc0[16], acc1[16];
    #pragma unroll
    for (int p = 0; p < 16; p++) { acc0[p] = 0ull; acc1[p] = 0ull; }

    for (int ch = 0; ch < 4; ch++) {
        __syncthreads();
        #pragma unroll
        for (int it = 0; it < 16; it++) {
            int item = it * TPB + tid;
            int r = item >> 3, q = item & 7;
            int gr = rowBase + r;
            float4 v = make_float4(0.f, 0.f, 0.f, 0.f);
            if (gr < nrows)
                v = *reinterpret_cast<const float4*>(&x[(size_t)gr * IN_FEAT + ch * 32 + q * 4]);
            int kk = q * 4;
            sBuf[(kk + 0) * SSTRIDE + r] = v.x;
            sBuf[(kk + 1) * SSTRIDE + r] = v.y;
            sBuf[(kk + 2) * SSTRIDE + r] = v.z;
            sBuf[(kk + 3) * SSTRIDE + r] = v.w;
        }
        __syncthreads();

        #pragma unroll 4
        for (int k = 0; k < 32; k++) {
            float2 xp = *reinterpret_cast<const float2*>(&sBuf[k * SSTRIDE + r0]);
            u64 x0 = pk2(xp.x, xp.x);
            u64 x1 = pk2(xp.y, xp.y);
            const ulonglong2* wr =
                reinterpret_cast<const ulonglong2*>(&sWc[(ch * 32 + k) * CODE_DIM]);
            #pragma unroll
            for (int q = 0; q < 8; q++) {
                ulonglong2 w = wr[q];
                acc0[2 * q]     = ffma2(x0, w.x, acc0[2 * q]);
                acc0[2 * q + 1] = ffma2(x0, w.y, acc0[2 * q + 1]);
                acc1[2 * q]     = ffma2(x1, w.x, acc1[2 * q]);
                acc1[2 * q + 1] = ffma2(x1, w.y, acc1[2 * q + 1]);
            }
        }
    }
    __syncthreads();

    // store z into sBuf (aliased): layout z[j][r]
    #pragma unroll
    for (int p = 0; p < 16; p++) {
        float a, b;
        upk2(acc0[p], a, b);
        sBuf[(2 * p) * SSTRIDE + r0]     = a;
        sBuf[(2 * p + 1) * SSTRIDE + r0] = b;
        upk2(acc1[p], a, b);
        sBuf[(2 * p) * SSTRIDE + r1]     = a;
        sBuf[(2 * p + 1) * SSTRIDE + r1] = b;
    }
    __syncthreads();

    // ---- phase B: dot = z @ cb^T (from ZERO; s0 added at the end -> low rounding noise),
    //      running argmax with second-best tracking (== argmin d2, first-index ties) ----
    float best0 = -3.402823466e38f, best1 = -3.402823466e38f;
    float sec0  = -3.402823466e38f, sec1  = -3.402823466e38f;
    int bi0 = 0, bi1 = 0;

    for (int cc = 0; cc < 8; cc++) {
        u64 sa0[16], sa1[16];
        #pragma unroll
        for (int p = 0; p < 16; p++) { sa0[p] = 0ull; sa1[p] = 0ull; }

        #pragma unroll 4
        for (int j = 0; j < CODE_DIM; j++) {
            float2 zp = *reinterpret_cast<const float2*>(&sBuf[j * SSTRIDE + r0]);
            u64 z0 = pk2(zp.x, zp.x);
            u64 z1 = pk2(zp.y, zp.y);
            const ulonglong2* cw =
                reinterpret_cast<const ulonglong2*>(&sCb[j * NUM_CODES + cc * 32]);
            #pragma unroll
            for (int q = 0; q < 8; q++) {
                ulonglong2 w = cw[q];
                sa0[2 * q]     = ffma2(z0, w.x, sa0[2 * q]);
                sa0[2 * q + 1] = ffma2(z0, w.y, sa0[2 * q + 1]);
                sa1[2 * q]     = ffma2(z1, w.x, sa1[2 * q]);
                sa1[2 * q + 1] = ffma2(z1, w.y, sa1[2 * q + 1]);
            }
        }
        #pragma unroll
        for (int p = 0; p < 16; p++) {
            float a, b;
            int c0 = cc * 32 + 2 * p;
            float s0a = sS0[c0], s0b = sS0[c0 + 1];
            upk2(sa0[p], a, b);
            a += s0a; b += s0b;
            if (a > best0) { sec0 = best0; best0 = a; bi0 = c0; }
            else if (a > sec0) sec0 = a;
            if (b > best0) { sec0 = best0; best0 = b; bi0 = c0 + 1; }
            else if (b > sec0) sec0 = b;
            upk2(sa1[p], a, b);
            a += s0a; b += s0b;
            if (a > best1) { sec1 = best1; best1 = a; bi1 = c0; }
            else if (a > sec1) sec1 = a;
            if (b > best1) { sec1 = best1; best1 = b; bi1 = c0 + 1; }
            else if (b > sec1) sec1 = b;
        }
    }

    sIdx[r0] = bi0;
    sIdx[r1] = bi1;

    // flag near-tie rows for fp64 refinement
    {
        int gr0 = rowBase + r0, gr1 = rowBase + r1;
        if (gr0 < nrows && best0 - sec0 < TIE_TH) {
            int p = atomicAdd(&g_cnt, 1);
            if (p < TIE_CAP) g_rows[p] = gr0;
        }
        if (gr1 < nrows && best1 - sec1 < TIE_TH) {
            int p = atomicAdd(&g_cnt, 1);
            if (p < TIE_CAP) g_rows[p] = gr1;
        }
    }
    __syncthreads();

    // ---- phase C: outputs ----
    float* yout = out;
    float* iout = out + (size_t)nrows * OUT_FEAT;
    const bool hasIdx = out_size >= (long long)nrows * (OUT_FEAT + 1);

    for (int i = 0; i < 64; i++) {
        int lr = rbase + i;
        int gr = rowBase + lr;
        if (gr < nrows) {
            int idx = sIdx[lr];
            float4 v = *reinterpret_cast<const float4*>(&g_T[idx * OUT_FEAT + lane * 4]);
            *reinterpret_cast<float4*>(&yout[(size_t)gr * OUT_FEAT + lane * 4]) = v;
        }
    }
    if (hasIdx) {
        for (int t = tid; t < RPB; t += TPB) {
            int gr = rowBase + t;
            if (gr < nrows) iout[gr] = (float)sIdx[t];
        }
    }
    if (blockIdx.x == 0 && tid == 0) {
        long long pos = (long long)nrows * OUT_FEAT + (hasIdx ? nrows : 0);
        for (long long p = pos; p < out_size; p++) out[p] = 0.0f;
    }
}

// =================== fp64 refinement for near-tie rows ===================

__global__ __launch_bounds__(256)
void k_refine(const float* __restrict__ x, const float* __restrict__ cb,
              float* __restrict__ out, int nrows, long long out_size) {
    int nt = g_cnt; if (nt > TIE_CAP) nt = TIE_CAP;
    const bool hasIdx = out_size >= (long long)nrows * (OUT_FEAT + 1);
    float* yout = out;
    float* iout = out + (size_t)nrows * OUT_FEAT;

    for (int i = blockIdx.x * blockDim.x + threadIdx.x; i < nt;
         i += gridDim.x * blockDim.x) {
        int gr = g_rows[i];

        // exact z (fp64 fused)
        double z[CODE_DIM];
        #pragma unroll
        for (int j = 0; j < CODE_DIM; j++) z[j] = g_bc64[j];
        const float* xr = &x[(size_t)gr * IN_FEAT];
        for (int k = 0; k < IN_FEAT; k++) {
            double xv = (double)xr[k];
            const double* wr = &g_Wc64[k * CODE_DIM];
            #pragma unroll
            for (int j = 0; j < CODE_DIM; j++) z[j] += xv * wr[j];
        }

        // exact argmin d2 (== argmax z.c - 0.5||c||^2), first-index tie-break
        double best = -1e300;
        int bi = 0;
        for (int c = 0; c < NUM_CODES; c++) {
            const float* cv = &cb[c * CODE_DIM];
            double s = 0.0, n2 = 0.0;
            #pragma unroll
            for (int j = 0; j < CODE_DIM; j++) {
                double v = (double)cv[j];
                s  += z[j] * v;
                n2 += v * v;
            }
            s -= 0.5 * n2;
            if (s > best) { best = s; bi = c; }
        }

        // rewrite outputs for this row
        for (int o = 0; o < OUT_FEAT; o++)
            yout[(size_t)gr * OUT_FEAT + o] = g_T[bi * OUT_FEAT + o];
        if (hasIdx) iout[gr] = (float)bi;
    }
}

// =================== launch ===================

extern "C" void kernel_launch(void* const* d_in, const int* in_sizes, int n_in,
                              void* d_out, int out_size) {
    const float* x   = (const float*)d_in[0];
    const float* Wd  = (const float*)d_in[1];
    const float* bd  = (const float*)d_in[2];
    const float* Wp  = (const float*)d_in[3];
    const float* bp  = (const float*)d_in[4];
    const float* cb  = (const float*)d_in[5];
    const float* Wpo = (const float*)d_in[6];
    const float* bpo = (const float*)d_in[7];
    const float* Wu  = (const float*)d_in[8];
    const float* bu  = (const float*)d_in[9];

    int nrows = in_sizes[0] / IN_FEAT;

    k_zero<<<1, 32>>>();
    k_pre_wc<<<8, 512>>>(Wd, bd, Wp, bp);
    k_pre_cb<<<16, 512>>>(cb);
    k_pre_U<<<64, 512>>>(cb, Wpo, bpo);
    k_pre_T<<<64, 512>>>(Wu, bu);

    const int smem_bytes = (4096 + 8192 + 256 + 32 * SSTRIDE) * 4 + RPB * 4;
    cudaFuncSetAttribute(k_main, cudaFuncAttributeMaxDynamicSharedMemorySize, smem_bytes);

    int blocks = (nrows + RPB - 1) / RPB;
    if (blocks > 0) {
        k_main<<<blocks, TPB, smem_bytes>>>(x, (float*)d_out, nrows, (long long)out_size);
        k_refine<<<128, 256>>>(x, cb, (float*)d_out, nrows, (long long)out_size);
    }
}

// round 4
// speedup vs baseline: 1.0086x; 1.0086x over previous
#include <cuda_runtime.h>
#include <cstdint>

#define IN_FEAT   128
#define CODE_DIM  32
#define NUM_CODES 256
#define OUT_FEAT  128

#define TPB 384            // threads per block (12 warps -> 170 reg/thread budget)
#define RPB 768            // rows per block (64 rows per warp, 2 per lane)
#define SSTRIDE 770        // smem row stride (floats), even for LDS.64 alignment

#define TIE_TH 5e-4f       // score-gap threshold for fp64 refinement
#define TIE_CAP (1 << 20)

// Precomputed fused parameters (device globals: no allocation allowed)
__device__ float  g_WcT[IN_FEAT * CODE_DIM];     // [m][j]  (W_pin @ W_down) transposed
__device__ double g_Wc64[IN_FEAT * CODE_DIM];    // fp64 copy for refinement
__device__ float  g_bc [CODE_DIM];               // W_pin @ b_down + b_pin
__device__ double g_bc64[CODE_DIM];
__device__ float  g_cbT[CODE_DIM * NUM_CODES];   // [j][c]  codebook transposed
__device__ float  g_s0 [NUM_CODES];              // cb.bc - 0.5*||cb||^2
__device__ float  g_U  [NUM_CODES * OUT_FEAT];   // cb @ W_pout^T + b_pout
__device__ float  g_T  [NUM_CODES * OUT_FEAT];   // clip(U @ W_up^T + b_up)
__device__ int    g_cnt;                          // near-tie row counter
__device__ int    g_rows[TIE_CAP];                // near-tie row list

// ---- packed f32x2 helpers (sm_103a) ----
using u64 = unsigned long long;
__device__ __forceinline__ u64 pk2(float lo, float hi) {
    u64 r; asm("mov.b64 %0,{%1,%2};" : "=l"(r) : "f"(lo), "f"(hi)); return r;
}
__device__ __forceinline__ void upk2(u64 v, float& lo, float& hi) {
    asm("mov.b64 {%0,%1},%2;" : "=f"(lo), "=f"(hi) : "l"(v));
}
__device__ __forceinline__ u64 ffma2(u64 a, u64 b, u64 c) {
    u64 d; asm("fma.rn.f32x2 %0,%1,%2,%3;" : "=l"(d) : "l"(a), "l"(b), "l"(c)); return d;
}

// =================== precompute kernels (tiny, fp64 accumulation) ===================

__global__ void k_zero() { if (threadIdx.x == 0 && blockIdx.x == 0) g_cnt = 0; }

__global__ void k_pre_wc(const float* __restrict__ Wd, const float* __restrict__ bd,
                         const float* __restrict__ Wp, const float* __restrict__ bp) {
    int t = blockIdx.x * blockDim.x + threadIdx.x;
    if (t < IN_FEAT * CODE_DIM) {
        int m = t >> 5, j = t & 31;
        double s = 0.0;
        for (int k = 0; k < IN_FEAT; k++)
            s += (double)Wp[j * IN_FEAT + k] * (double)Wd[k * IN_FEAT + m];
        g_WcT[m * CODE_DIM + j]  = (float)s;
        g_Wc64[m * CODE_DIM + j] = s;
    }
    if (t < CODE_DIM) {
        double s = (double)bp[t];
        for (int k = 0; k < IN_FEAT; k++)
            s += (double)Wp[t * IN_FEAT + k] * (double)bd[k];
        g_bc[t]   = (float)s;
        g_bc64[t] = s;
    }
}

__global__ void k_pre_cb(const float* __restrict__ cb) {
    int t = blockIdx.x * blockDim.x + threadIdx.x;
    if (t < CODE_DIM * NUM_CODES) {
        int j = t >> 8, c = t & 255;
        g_cbT[j * NUM_CODES + c] = cb[c * CODE_DIM + j];
    }
    if (t < NUM_CODES) {
        double s = 0.0, n2 = 0.0;
        for (int j = 0; j < CODE_DIM; j++) {
            double v = (double)cb[t * CODE_DIM + j];
            s  += v * g_bc64[j];
            n2 += v * v;
        }
        g_s0[t] = (float)(s - 0.5 * n2);
    }
}

__global__ void k_pre_U(const float* __restrict__ cb, const float* __restrict__ Wpo,
                        const float* __restrict__ bpo) {
    int t = blockIdx.x * blockDim.x + threadIdx.x;   // 32768
    int c = t >> 7, o = t & 127;
    float s = bpo[o];
    for (int j = 0; j < CODE_DIM; j++)
        s = fmaf(cb[c * CODE_DIM + j], Wpo[o * CODE_DIM + j], s);
    g_U[c * OUT_FEAT + o] = s;
}

__global__ void k_pre_T(const float* __restrict__ Wu, const float* __restrict__ bu) {
    int t = blockIdx.x * blockDim.x + threadIdx.x;   // 32768
    int c = t >> 7, o = t & 127;
    float s = bu[o];
    for (int i = 0; i < OUT_FEAT; i++)
        s = fmaf(g_U[c * OUT_FEAT + i], Wu[o * OUT_FEAT + i], s);
    g_T[c * OUT_FEAT + o] = fminf(fmaxf(s, -1.0f), 1.0f);
}

// =================== main kernel ===================

__global__ __launch_bounds__(TPB, 1)
void k_main(const float* __restrict__ x, float* __restrict__ out,
            int nrows, long long out_size) {
    extern __shared__ float sm[];
    float* sWc  = sm;                       // 4096 floats  [k][j]
    float* sCb  = sWc + 4096;               // 8192 floats  [j][c]
    float* sS0  = sCb + 8192;               // 256 floats
    float* sBuf = sS0 + 256;                // 32*SSTRIDE floats (x-chunk / z, aliased)
    int*   sIdx = (int*)(sBuf + 32 * SSTRIDE);  // RPB ints

    const int tid  = threadIdx.x;
    const int wid  = tid >> 5;
    const int lane = tid & 31;
    const int rowBase = blockIdx.x * RPB;

    for (int i = tid; i < 4096; i += TPB) sWc[i] = g_WcT[i];
    for (int i = tid; i < 8192; i += TPB) sCb[i] = g_cbT[i];
    if (tid < 256) sS0[tid] = g_s0[tid];

    const int rbase = wid * 64;
    const int r0 = rbase + 2 * lane;
    const int r1 = r0 + 1;

    // ---- phase A: z = x @ Wc^T (2 rows/thread, 32 outputs packed as 16 f32x2) ----
    u64 acc0[16], acc1[16];
    #pragma unroll
    for (int p = 0; p < 16; p++) { acc0[p] = 0ull; acc1[p] = 0ull; }

    for (int ch = 0; ch < 4; ch++) {
        __syncthreads();
        // cooperative load + transpose of x chunk [32k x RPB rows]
        // unroll 2 only: caps in-flight LDG registers (reg-pressure control)
        #pragma unroll 2
        for (int it = 0; it < 16; it++) {
            int item = it * TPB + tid;
            int r = item >> 3, q = item & 7;
            int gr = rowBase + r;
            float4 v = make_float4(0.f, 0.f, 0.f, 0.f);
            if (gr < nrows)
                v = *reinterpret_cast<const float4*>(&x[(size_t)gr * IN_FEAT + ch * 32 + q * 4]);
            int kk = q * 4;
            sBuf[(kk + 0) * SSTRIDE + r] = v.x;
            sBuf[(kk + 1) * SSTRIDE + r] = v.y;
            sBuf[(kk + 2) * SSTRIDE + r] = v.z;
            sBuf[(kk + 3) * SSTRIDE + r] = v.w;
        }
        __syncthreads();

        #pragma unroll 4
        for (int k = 0; k < 32; k++) {
            float2 xp = *reinterpret_cast<const float2*>(&sBuf[k * SSTRIDE + r0]);
            u64 x0 = pk2(xp.x, xp.x);
            u64 x1 = pk2(xp.y, xp.y);
            const ulonglong2* wr =
                reinterpret_cast<const ulonglong2*>(&sWc[(ch * 32 + k) * CODE_DIM]);
            #pragma unroll
            for (int q = 0; q < 8; q++) {
                ulonglong2 w = wr[q];
                acc0[2 * q]     = ffma2(x0, w.x, acc0[2 * q]);
                acc0[2 * q + 1] = ffma2(x0, w.y, acc0[2 * q + 1]);
                acc1[2 * q]     = ffma2(x1, w.x, acc1[2 * q]);
                acc1[2 * q + 1] = ffma2(x1, w.y, acc1[2 * q + 1]);
            }
        }
    }
    __syncthreads();

    // store z into sBuf (aliased): layout z[j][r]
    #pragma unroll
    for (int p = 0; p < 16; p++) {
        float a, b;
        upk2(acc0[p], a, b);
        sBuf[(2 * p) * SSTRIDE + r0]     = a;
        sBuf[(2 * p + 1) * SSTRIDE + r0] = b;
        upk2(acc1[p], a, b);
        sBuf[(2 * p) * SSTRIDE + r1]     = a;
        sBuf[(2 * p + 1) * SSTRIDE + r1] = b;
    }
    __syncthreads();

    // ---- phase B: dot = z @ cb^T (from ZERO; s0 added at the end),
    //      running argmax with second-best tracking (== argmin d2, first-index ties) ----
    float best0 = -3.402823466e38f, best1 = -3.402823466e38f;
    float sec0  = -3.402823466e38f, sec1  = -3.402823466e38f;
    int bi0 = 0, bi1 = 0;

    for (int cc = 0; cc < 8; cc++) {
        u64 sa0[16], sa1[16];
        #pragma unroll
        for (int p = 0; p < 16; p++) { sa0[p] = 0ull; sa1[p] = 0ull; }

        #pragma unroll 4
        for (int j = 0; j < CODE_DIM; j++) {
            float2 zp = *reinterpret_cast<const float2*>(&sBuf[j * SSTRIDE + r0]);
            u64 z0 = pk2(zp.x, zp.x);
            u64 z1 = pk2(zp.y, zp.y);
            const ulonglong2* cw =
                reinterpret_cast<const ulonglong2*>(&sCb[j * NUM_CODES + cc * 32]);
            #pragma unroll
            for (int q = 0; q < 8; q++) {
                ulonglong2 w = cw[q];
                sa0[2 * q]     = ffma2(z0, w.x, sa0[2 * q]);
                sa0[2 * q + 1] = ffma2(z0, w.y, sa0[2 * q + 1]);
                sa1[2 * q]     = ffma2(z1, w.x, sa1[2 * q]);
                sa1[2 * q + 1] = ffma2(z1, w.y, sa1[2 * q + 1]);
            }
        }
        #pragma unroll
        for (int p = 0; p < 16; p++) {
            float a, b;
            int c0 = cc * 32 + 2 * p;
            float s0a = sS0[c0], s0b = sS0[c0 + 1];
            upk2(sa0[p], a, b);
            a += s0a; b += s0b;
            if (a > best0) { sec0 = best0; best0 = a; bi0 = c0; }
            else if (a > sec0) sec0 = a;
            if (b > best0) { sec0 = best0; best0 = b; bi0 = c0 + 1; }
            else if (b > sec0) sec0 = b;
            upk2(sa1[p], a, b);
            a += s0a; b += s0b;
            if (a > best1) { sec1 = best1; best1 = a; bi1 = c0; }
            else if (a > sec1) sec1 = a;
            if (b > best1) { sec1 = best1; best1 = b; bi1 = c0 + 1; }
            else if (b > sec1) sec1 = b;
        }
    }

    sIdx[r0] = bi0;
    sIdx[r1] = bi1;

    // flag near-tie rows for fp64 refinement
    {
        int gr0 = rowBase + r0, gr1 = rowBase + r1;
        if (gr0 < nrows && best0 - sec0 < TIE_TH) {
            int p = atomicAdd(&g_cnt, 1);
            if (p < TIE_CAP) g_rows[p] = gr0;
        }
        if (gr1 < nrows && best1 - sec1 < TIE_TH) {
            int p = atomicAdd(&g_cnt, 1);
            if (p < TIE_CAP) g_rows[p] = gr1;
        }
    }
    __syncthreads();

    // ---- phase C: outputs ----
    float* yout = out;
    float* iout = out + (size_t)nrows * OUT_FEAT;
    const bool hasIdx = out_size >= (long long)nrows * (OUT_FEAT + 1);

    #pragma unroll 4
    for (int i = 0; i < 64; i++) {
        int lr = rbase + i;
        int gr = rowBase + lr;
        if (gr < nrows) {
            int idx = sIdx[lr];
            float4 v = *reinterpret_cast<const float4*>(&g_T[idx * OUT_FEAT + lane * 4]);
            *reinterpret_cast<float4*>(&yout[(size_t)gr * OUT_FEAT + lane * 4]) = v;
        }
    }
    if (hasIdx) {
        for (int t = tid; t < RPB; t += TPB) {
            int gr = rowBase + t;
            if (gr < nrows) iout[gr] = (float)sIdx[t];
        }
    }
    if (blockIdx.x == 0 && tid == 0) {
        long long pos = (long long)nrows * OUT_FEAT + (hasIdx ? nrows : 0);
        for (long long p = pos; p < out_size; p++) out[p] = 0.0f;
    }
}

// =================== fp64 refinement for near-tie rows ===================

__global__ __launch_bounds__(256)
void k_refine(const float* __restrict__ x, const float* __restrict__ cb,
              float* __restrict__ out, int nrows, long long out_size) {
    int nt = g_cnt; if (nt > TIE_CAP) nt = TIE_CAP;
    const bool hasIdx = out_size >= (long long)nrows * (OUT_FEAT + 1);
    float* yout = out;
    float* iout = out + (size_t)nrows * OUT_FEAT;

    for (int i = blockIdx.x * blockDim.x + threadIdx.x; i < nt;
         i += gridDim.x * blockDim.x) {
        int gr = g_rows[i];

        // exact z (fp64 fused)
        double z[CODE_DIM];
        #pragma unroll
        for (int j = 0; j < CODE_DIM; j++) z[j] = g_bc64[j];
        const float* xr = &x[(size_t)gr * IN_FEAT];
        for (int k = 0; k < IN_FEAT; k++) {
            double xv = (double)xr[k];
            const double* wr = &g_Wc64[k * CODE_DIM];
            #pragma unroll
            for (int j = 0; j < CODE_DIM; j++) z[j] += xv * wr[j];
        }

        // exact argmin d2 (== argmax z.c - 0.5||c||^2), first-index tie-break
        double best = -1e300;
        int bi = 0;
        for (int c = 0; c < NUM_CODES; c++) {
            const float* cv = &cb[c * CODE_DIM];
            double s = 0.0, n2 = 0.0;
            #pragma unroll
            for (int j = 0; j < CODE_DIM; j++) {
                double v = (double)cv[j];
                s  += z[j] * v;
                n2 += v * v;
            }
            s -= 0.5 * n2;
            if (s > best) { best = s; bi = c; }
        }

        // rewrite outputs for this row
        for (int o = 0; o < OUT_FEAT; o++)
            yout[(size_t)gr * OUT_FEAT + o] = g_T[bi * OUT_FEAT + o];
        if (hasIdx) iout[gr] = (float)bi;
    }
}

// =================== launch ===================

extern "C" void kernel_launch(void* const* d_in, const int* in_sizes, int n_in,
                              void* d_out, int out_size) {
    const float* x   = (const float*)d_in[0];
    const float* Wd  = (const float*)d_in[1];
    const float* bd  = (const float*)d_in[2];
    const float* Wp  = (const float*)d_in[3];
    const float* bp  = (const float*)d_in[4];
    const float* cb  = (const float*)d_in[5];
    const float* Wpo = (const float*)d_in[6];
    const float* bpo = (const float*)d_in[7];
    const float* Wu  = (const float*)d_in[8];
    const float* bu  = (const float*)d_in[9];

    int nrows = in_sizes[0] / IN_FEAT;

    k_zero<<<1, 32>>>();
    k_pre_wc<<<8, 512>>>(Wd, bd, Wp, bp);
    k_pre_cb<<<16, 512>>>(cb);
    k_pre_U<<<64, 512>>>(cb, Wpo, bpo);
    k_pre_T<<<64, 512>>>(Wu, bu);

    const int smem_bytes = (4096 + 8192 + 256 + 32 * SSTRIDE) * 4 + RPB * 4;  // 151808 B
    cudaFuncSetAttribute(k_main, cudaFuncAttributeMaxDynamicSharedMemorySize, smem_bytes);

    int blocks = (nrows + RPB - 1) / RPB;
    if (blocks > 0) {
        k_main<<<blocks, TPB, smem_bytes>>>(x, (float*)d_out, nrows, (long long)out_size);
        k_refine<<<128, 256>>>(x, cb, (float*)d_out, nrows, (long long)out_size);
    }
}